// round 15
// baseline (speedup 1.0000x reference)
#include <cuda_runtime.h>
#include <cstdint>

// FINAL: y[b, i, c] = x[b, i+1, c] - x[b, i, c]
// x: [B=64, L=16384, C=32] fp32, y: [B, L-1, C] fp32
// v8 = 8 fp32 = 32 B (Blackwell 256-bit ld/st). Row = 128 B = 4 v8; shift = +4 v8.
//
// Champion config (R8/R13: kernel ~37.0us = ~6.9 TB/s DRAM ~87% of spec):
//  - lane-contiguous layout, i = base + tid + k*TPB in v8 units
//      (R4: per-thread consecutive chunks destroyed coalescing, +60% time)
//  - plain ld.global.v8.b32 loads
//      (R6: load evict_first regressed; R11: RO-path __ldg regressed)
//  - st.global.L2::evict_first.v8.b32 stores
//      (R7: bench win — early writeback of never-re-read output lines)
//  - VPT=2, TPB=256 (TPB=512, VPT=4 measured neutral)
// R14 change: tail branch removed via index clamp. The 4 OOB v8s per batch
// clamp to OUT-1 and redundantly store byte-identical values (benign duplicate
// write) — uniform warps, half the code size, no guarded path.

static constexpr int B = 64;
static constexpr int L = 16384;
static constexpr int C = 32;
static constexpr int IN_V8_PER_B  = L * C / 8;        // 65536
static constexpr int OUT_V8_PER_B = (L - 1) * C / 8;  // 65532
static constexpr int VPT = 2;                         // v8 chunks per thread (strided)
static constexpr int TPB = 256;
static constexpr int V8_PER_BLOCK = VPT * TPB;        // 512

struct V8 { float v[8]; };

__device__ __forceinline__ void ldg_v8(const float* p, V8& r) {
    asm volatile(
        "ld.global.v8.b32 {%0,%1,%2,%3,%4,%5,%6,%7}, [%8];"
        : "=f"(r.v[0]), "=f"(r.v[1]), "=f"(r.v[2]), "=f"(r.v[3]),
          "=f"(r.v[4]), "=f"(r.v[5]), "=f"(r.v[6]), "=f"(r.v[7])
        : "l"(p));
}

__device__ __forceinline__ void stg_ef_v8(float* p, const V8& r) {
    asm volatile(
        "st.global.L2::evict_first.v8.b32 [%0], {%1,%2,%3,%4,%5,%6,%7,%8};"
        :: "l"(p),
           "f"(r.v[0]), "f"(r.v[1]), "f"(r.v[2]), "f"(r.v[3]),
           "f"(r.v[4]), "f"(r.v[5]), "f"(r.v[6]), "f"(r.v[7])
        : "memory");
}

__global__ void __launch_bounds__(TPB) diff1d_kernel(
    const float* __restrict__ x, float* __restrict__ y)
{
    const int b = blockIdx.y;
    const float* __restrict__ xin = x + (size_t)b * (IN_V8_PER_B * 8);
    float* __restrict__ yout = y + (size_t)b * (OUT_V8_PER_B * 8);

    const int base = blockIdx.x * V8_PER_BLOCK + threadIdx.x;  // in v8 units

    // Uniform body: clamp the (rare) OOB indexes to the last valid chunk.
    // Clamped threads duplicate the owner's work with identical bytes.
    int idx[VPT];
    V8 a[VPT], bb[VPT];
#pragma unroll
    for (int k = 0; k < VPT; k++) {
        int i = base + k * TPB;
        idx[k] = i < (OUT_V8_PER_B - 1) ? i : (OUT_V8_PER_B - 1);
        ldg_v8(xin + (size_t)idx[k] * 8, a[k]);
        ldg_v8(xin + (size_t)(idx[k] + 4) * 8, bb[k]);  // +4 v8 = next row along L
    }
#pragma unroll
    for (int k = 0; k < VPT; k++) {
        V8 r;
#pragma unroll
        for (int j = 0; j < 8; j++) r.v[j] = bb[k].v[j] - a[k].v[j];
        stg_ef_v8(yout + (size_t)idx[k] * 8, r);
    }
}

extern "C" void kernel_launch(void* const* d_in, const int* in_sizes, int n_in,
                              void* d_out, int out_size)
{
    (void)in_sizes; (void)n_in; (void)out_size;
    const float* x = (const float*)d_in[0];
    float* y = (float*)d_out;

    dim3 block(TPB);
    dim3 grid((OUT_V8_PER_B + V8_PER_BLOCK - 1) / V8_PER_BLOCK, B);  // (128, 64)
    diff1d_kernel<<<grid, block>>>(x, y);
}

// round 17
// speedup vs baseline: 1.0050x; 1.0050x over previous
#include <cuda_runtime.h>
#include <cstdint>

// FINAL (champion, converged): y[b, i, c] = x[b, i+1, c] - x[b, i, c]
// x: [B=64, L=16384, C=32] fp32, y: [B, L-1, C] fp32
// v8 = 8 fp32 = 32 B (Blackwell 256-bit ld/st). Row = 128 B = 4 v8; shift = +4 v8.
//
// Measured at kernel 36.96us = 6.93 TB/s DRAM = ~87% of 8 TB/s spec (roofline).
// (R15 run was a broker/container infra failure on this exact source, which
//  previously passed twice — resubmitted unchanged.)
// Session evidence baked into this config:
//  - lane-contiguous layout, i = base + tid + k*TPB in v8 units
//      (R4: per-thread consecutive chunks destroyed coalescing, +60% time)
//  - plain ld.global.v8.b32 loads
//      (R6: load evict_first regressed; R11: RO-path __ldg regressed)
//  - st.global.L2::evict_first.v8.b32 stores
//      (R7: reproducible bench win — early writeback of never-re-read output)
//  - VPT=2, TPB=256 (VPT=4, TPB=512 measured neutral; low regs -> occ 56%)
//  - uniform clamped body (R14: ties best kernel time, no tail branch; the 4
//    clamped OOB v8s per batch redundantly store byte-identical values)

static constexpr int B = 64;
static constexpr int L = 16384;
static constexpr int C = 32;
static constexpr int IN_V8_PER_B  = L * C / 8;        // 65536
static constexpr int OUT_V8_PER_B = (L - 1) * C / 8;  // 65532
static constexpr int VPT = 2;                         // v8 chunks per thread (strided)
static constexpr int TPB = 256;
static constexpr int V8_PER_BLOCK = VPT * TPB;        // 512

struct V8 { float v[8]; };

__device__ __forceinline__ void ldg_v8(const float* p, V8& r) {
    asm volatile(
        "ld.global.v8.b32 {%0,%1,%2,%3,%4,%5,%6,%7}, [%8];"
        : "=f"(r.v[0]), "=f"(r.v[1]), "=f"(r.v[2]), "=f"(r.v[3]),
          "=f"(r.v[4]), "=f"(r.v[5]), "=f"(r.v[6]), "=f"(r.v[7])
        : "l"(p));
}

__device__ __forceinline__ void stg_ef_v8(float* p, const V8& r) {
    asm volatile(
        "st.global.L2::evict_first.v8.b32 [%0], {%1,%2,%3,%4,%5,%6,%7,%8};"
        :: "l"(p),
           "f"(r.v[0]), "f"(r.v[1]), "f"(r.v[2]), "f"(r.v[3]),
           "f"(r.v[4]), "f"(r.v[5]), "f"(r.v[6]), "f"(r.v[7])
        : "memory");
}

__global__ void __launch_bounds__(TPB) diff1d_kernel(
    const float* __restrict__ x, float* __restrict__ y)
{
    const int b = blockIdx.y;
    const float* __restrict__ xin = x + (size_t)b * (IN_V8_PER_B * 8);
    float* __restrict__ yout = y + (size_t)b * (OUT_V8_PER_B * 8);

    const int base = blockIdx.x * V8_PER_BLOCK + threadIdx.x;  // in v8 units

    // Uniform body: clamp the (rare) OOB indexes to the last valid chunk.
    // Clamped threads duplicate the owner's work with identical bytes.
    int idx[VPT];
    V8 a[VPT], bb[VPT];
#pragma unroll
    for (int k = 0; k < VPT; k++) {
        int i = base + k * TPB;
        idx[k] = i < (OUT_V8_PER_B - 1) ? i : (OUT_V8_PER_B - 1);
        ldg_v8(xin + (size_t)idx[k] * 8, a[k]);
        ldg_v8(xin + (size_t)(idx[k] + 4) * 8, bb[k]);  // +4 v8 = next row along L
    }
#pragma unroll
    for (int k = 0; k < VPT; k++) {
        V8 r;
#pragma unroll
        for (int j = 0; j < 8; j++) r.v[j] = bb[k].v[j] - a[k].v[j];
        stg_ef_v8(yout + (size_t)idx[k] * 8, r);
    }
}

extern "C" void kernel_launch(void* const* d_in, const int* in_sizes, int n_in,
                              void* d_out, int out_size)
{
    (void)in_sizes; (void)n_in; (void)out_size;
    const float* x = (const float*)d_in[0];
    float* y = (float*)d_out;

    dim3 block(TPB);
    dim3 grid((OUT_V8_PER_B + V8_PER_BLOCK - 1) / V8_PER_BLOCK, B);  // (128, 64)
    diff1d_kernel<<<grid, block>>>(x, y);
}